// round 16
// baseline (speedup 1.0000x reference)
#include <cuda_runtime.h>

// ---------------- problem constants ----------------
#define O   130          // output spatial extent per axis
#define P   (O*O)        // 16900
#define O3  2197000      // 130^3
#define CH  12
// input x is 128^3

// ---------------- scratch (device globals) ----------------
// channel-quad layout: g_buf4[((q*O + z)*P + y*O + w)] = 4 permuted channels
__device__ float4 g_buf4[(size_t)3 * O3];
__device__ float  g_partial[10 * 67];
__device__ float  g_clip[2];

// shift offsets (oz, oy, ow) for the 6 one-hot dilated stencils, padded coords
__device__ constexpr int OFFS[6][3] = {
    {-1, 1, 1},   // s0: z-minus
    { 1, 1,-1},   // s1: w-minus
    { 1,-1, 1},   // s2: y-minus
    { 1, 1, 3},   // s3: w-plus
    { 3, 1, 1},   // s4: z-plus
    { 1, 3, 1}    // s5: y-plus
};
// quad partition of the 12 pairs: each quad spans exactly 4 shifts
__device__ constexpr int QS[3][4] = {        // shift ids per quad
    {0, 1, 2, 3},
    {0, 3, 4, 5},
    {1, 2, 4, 5}
};
__device__ constexpr int QP[3][4][2] = {     // channel pairs as local indices into QS[qd]
    { {1,0}, {2,0}, {2,1}, {3,2} },   // (1,0) (2,0) (2,1) (3,2)
    { {1,0}, {2,1}, {3,0}, {3,1} },   // (3,0) (4,3) (5,0) (5,3)
    { {2,0}, {2,1}, {3,0}, {3,2} }    // (4,1) (4,2) (5,1) (5,4)
};
// output channel id of each quad lane
__constant__ int CHMAP[12] = {0,1,2,4,  3,7,8,10,  5,6,9,11};

// ---------------- K1: 3 src planes -> quad diff^2 -> W-box -> H-box ------------
#define STRIP 10
#define SR    14           // STRIP + 4 boxed halo rows
#define NSTRIP 13          // 13*10 = 130
#define RY    18           // padded-y source rows: jy in [y0-3, y0+14]
#define SXN   (3*RY*134)   // 7236 floats
#define SRN   (SR*O)       // 1820 floats per row buffer
#define K1_SMEM ((SXN + 4*SRN) * 4)   // 58.1 KB

__global__ __launch_bounds__(256) void k1_kernel(const float* __restrict__ x) {
    extern __shared__ float sm[];
    float* s_x = sm;                       // [3][RY][134]
    float* s_r[4] = { sm + SXN, sm + SXN + SRN,
                      sm + SXN + 2*SRN, sm + SXN + 3*SRN };  // [SR][O] each

    const int z   = blockIdx.y;
    const int y0  = blockIdx.x * STRIP;
    const int jy0 = y0 - 3;
    const int tid = threadIdx.x;

    // ---- fill 3 padded source planes (jz = z-1, z+1, z+3), one warp per row ----
    {
        const int wid  = tid >> 5;
        const int lane = tid & 31;
        for (int row = wid; row < 3 * RY; row += 8) {
            int p  = row / RY;
            int ry = row - p * RY;
            int jz = z + 2 * p - 1;
            int jy = jy0 + ry;
            bool rowok = (jz >= 0) & (jz <= 131) & (jy >= 0) & (jy <= 131);
            const float* xrow = x + ((size_t)min(max(jz - 2, 0), 127) << 14)
                                  + (min(max(jy - 2, 0), 127) << 7);
            float* srow = &s_x[(p * RY + ry) * 134];
            #pragma unroll
            for (int k = 0; k < 5; k++) {
                int i = lane + 32 * k;
                if (i < 134) {
                    bool ok = rowok & (i >= 1) & (i <= 132);
                    float v = 0.0f;
                    if (ok) v = __ldg(&xrow[min(max(i - 3, 0), 127)]);
                    srow[i] = v;
                }
            }
        }
    }
    __syncthreads();

    #pragma unroll
    for (int qd = 0; qd < 3; qd++) {
        // ---- W-box: 4 shift rows shared across 4 channels ----
        for (int idx = tid; idx < SR * NSTRIP; idx += 256) {
            int r  = idx / NSTRIP;
            int sg = idx - r * NSTRIP;
            int w0 = sg * 10;
            int ay = min(max(y0 - 2 + r, 0), O - 1);

            const float* R[4];
            #pragma unroll
            for (int l = 0; l < 4; l++) {
                const int s  = QS[qd][l];
                const int p  = (OFFS[s][0] + 1) >> 1;
                R[l] = &s_x[(p * RY + ay + OFFS[s][1] - jy0) * 134 + OFFS[s][2] + 1];
            }

            float d2[4][14];
            #pragma unroll
            for (int k = 0; k < 14; k++) {
                int ww = min(max(w0 - 2 + k, 0), O - 1);
                float v[4];
                v[0] = R[0][ww]; v[1] = R[1][ww]; v[2] = R[2][ww]; v[3] = R[3][ww];
                #pragma unroll
                for (int j = 0; j < 4; j++) {
                    float d = v[QP[qd][j][0]] - v[QP[qd][j][1]];
                    d2[j][k] = d * d;
                }
            }

            float s0 = d2[0][0] + d2[0][1] + d2[0][2] + d2[0][3] + d2[0][4];
            float s1 = d2[1][0] + d2[1][1] + d2[1][2] + d2[1][3] + d2[1][4];
            float s2 = d2[2][0] + d2[2][1] + d2[2][2] + d2[2][3] + d2[2][4];
            float s3 = d2[3][0] + d2[3][1] + d2[3][2] + d2[3][3] + d2[3][4];
            float* p0 = &s_r[0][r * O + w0];
            float* p1 = &s_r[1][r * O + w0];
            float* p2 = &s_r[2][r * O + w0];
            float* p3 = &s_r[3][r * O + w0];
            #pragma unroll
            for (int j = 0; j < 10; j++) {
                p0[j] = s0; p1[j] = s1; p2[j] = s2; p3[j] = s3;
                if (j < 9) {
                    s0 += d2[0][j + 5] - d2[0][j];
                    s1 += d2[1][j + 5] - d2[1][j];
                    s2 += d2[2][j + 5] - d2[2][j];
                    s3 += d2[3][j + 5] - d2[3][j];
                }
            }
        }
        __syncthreads();

        // ---- H-box for 4 channels, write float4 ----
        float4* gb = &g_buf4[((size_t)qd * O + z) * P + (size_t)y0 * O];
        for (int idx = tid; idx < 2 * O; idx += 256) {
            int w   = idx % O;
            int ry0 = (idx / O) * 5;
            float t0[9], t1[9], t2[9], t3[9];
            #pragma unroll
            for (int k = 0; k < 9; k++) {
                t0[k] = s_r[0][(ry0 + k) * O + w];
                t1[k] = s_r[1][(ry0 + k) * O + w];
                t2[k] = s_r[2][(ry0 + k) * O + w];
                t3[k] = s_r[3][(ry0 + k) * O + w];
            }
            float s0 = t0[0] + t0[1] + t0[2] + t0[3] + t0[4];
            float s1 = t1[0] + t1[1] + t1[2] + t1[3] + t1[4];
            float s2 = t2[0] + t2[1] + t2[2] + t2[3] + t2[4];
            float s3 = t3[0] + t3[1] + t3[2] + t3[3] + t3[4];
            #pragma unroll
            for (int j = 0; j < 5; j++) {
                gb[(ry0 + j) * O + w] = make_float4(s0, s1, s2, s3);
                if (j < 4) {
                    s0 += t0[j + 5] - t0[j];
                    s1 += t1[j + 5] - t1[j];
                    s2 += t2[j + 5] - t2[j];
                    s3 += t3[j + 5] - t3[j];
                }
            }
        }
        __syncthreads();
    }
}

// ---------------- K2: z-box sweep, ring window, unroll-4 (ring period) ---------
#define ZCH  10
#define ZLEN 13
#define PBLK 67   // ceil(16900/256)

__global__ __launch_bounds__(256) void k2_kernel(float* __restrict__ mind) {
    const int tid = threadIdx.x;
    const int v   = blockIdx.x * 256 + tid;
    const int z0  = blockIdx.y * ZLEN;
    const int z1  = min(z0 + ZLEN, O);
    float acc = 0.0f;

    if (v < P) {
        float sums[CH], w0[CH], w1[CH], w2[CH], w3[CH];
        #pragma unroll
        for (int c = 0; c < CH; c++) sums[c] = 0.0f;

        #pragma unroll
        for (int q = 0; q < 4; q++) {
            int pz = min(max(z0 - 2 + q, 0), O - 1);
            float t[CH];
            #pragma unroll
            for (int qd = 0; qd < 3; qd++) {
                float4 u = g_buf4[((size_t)qd * O + pz) * P + v];
                t[4*qd] = u.x; t[4*qd+1] = u.y; t[4*qd+2] = u.z; t[4*qd+3] = u.w;
            }
            #pragma unroll
            for (int c = 0; c < CH; c++) {
                sums[c] += t[c];
                if (q == 0) w0[c] = t[c];
                else if (q == 1) w1[c] = t[c];
                else if (q == 2) w2[c] = t[c];
                else w3[c] = t[c];
            }
        }

        #pragma unroll 4
        for (int z = z0; z < z1; z++) {
            int pz = min(z + 2, O - 1);
            float nv[CH];
            #pragma unroll
            for (int qd = 0; qd < 3; qd++) {
                float4 u = g_buf4[((size_t)qd * O + pz) * P + v];
                nv[4*qd] = u.x; nv[4*qd+1] = u.y; nv[4*qd+2] = u.z; nv[4*qd+3] = u.w;
            }
            #pragma unroll
            for (int c = 0; c < CH; c++) sums[c] += nv[c];

            float mn = sums[0], tot = sums[0];
            #pragma unroll
            for (int c = 1; c < CH; c++) { mn = fminf(mn, sums[c]); tot += sums[c]; }

            // write each permuted lane to its true output channel
            #pragma unroll
            for (int c = 0; c < CH; c++)
                mind[(size_t)CHMAP[c] * O3 + (size_t)z * P + v] =
                    (sums[c] - mn) * (1.0f / 125.0f);

            acc += (tot * (1.0f / 12.0f) - mn) * (1.0f / 125.0f);

            #pragma unroll
            for (int c = 0; c < CH; c++) {
                sums[c] -= w0[c];
                w0[c] = w1[c]; w1[c] = w2[c]; w2[c] = w3[c]; w3[c] = nv[c];
            }
        }
    }

    __shared__ float red[256];
    red[tid] = acc;
    __syncthreads();
    for (int s = 128; s > 0; s >>= 1) {
        if (tid < s) red[tid] += red[tid + s];
        __syncthreads();
    }
    if (tid == 0) g_partial[blockIdx.y * PBLK + blockIdx.x] = red[0];
}

// ---------------- K2b: deterministic final reduction -> clip bounds ------------
__global__ void k2b_kernel() {
    __shared__ float red[256];
    const int tid = threadIdx.x;
    float a = 0.0f;
    for (int i = tid; i < ZCH * PBLK; i += 256) a += g_partial[i];
    red[tid] = a;
    __syncthreads();
    for (int s = 128; s > 0; s >>= 1) {
        if (tid < s) red[tid] += red[tid + s];
        __syncthreads();
    }
    if (tid == 0) {
        float mean = red[0] / (float)O3;
        g_clip[0] = mean * 0.001f;
        g_clip[1] = mean * 1000.0f;
    }
}

// ---------------- K3: recompute var from channels, exp, float4 ----------------
#define Q4 (O3 / 4)    // 549250

__global__ __launch_bounds__(256) void k3_kernel(float* __restrict__ out) {
    const int v4 = blockIdx.x * 256 + threadIdx.x;
    if (v4 >= Q4) return;
    float4* o4 = (float4*)out;

    float4 m[CH];
    #pragma unroll
    for (int c = 0; c < CH; c++) m[c] = o4[(size_t)c * Q4 + v4];

    float sx = 0.f, sy = 0.f, sz = 0.f, sw = 0.f;
    #pragma unroll
    for (int c = 0; c < CH; c++) {
        sx += m[c].x; sy += m[c].y; sz += m[c].z; sw += m[c].w;
    }
    const float lo = g_clip[0], hi = g_clip[1];
    float ix = 1.0f / fminf(fmaxf(sx * (1.0f/12.0f), lo), hi);
    float iy = 1.0f / fminf(fmaxf(sy * (1.0f/12.0f), lo), hi);
    float iz = 1.0f / fminf(fmaxf(sz * (1.0f/12.0f), lo), hi);
    float iw = 1.0f / fminf(fmaxf(sw * (1.0f/12.0f), lo), hi);

    #pragma unroll
    for (int c = 0; c < CH; c++) {
        float4 r;
        r.x = __expf(-m[c].x * ix);
        r.y = __expf(-m[c].y * iy);
        r.z = __expf(-m[c].z * iz);
        r.w = __expf(-m[c].w * iw);
        o4[(size_t)c * Q4 + v4] = r;
    }
}

// ---------------- launch ----------------
extern "C" void kernel_launch(void* const* d_in, const int* in_sizes, int n_in,
                              void* d_out, int out_size) {
    const float* x = (const float*)d_in[0];
    float* out = (float*)d_out;

    cudaFuncSetAttribute(k1_kernel,
                         cudaFuncAttributeMaxDynamicSharedMemorySize, K1_SMEM);

    dim3 g1(NSTRIP, O);
    k1_kernel<<<g1, 256, K1_SMEM>>>(x);

    dim3 g2(PBLK, ZCH);
    k2_kernel<<<g2, 256>>>(out);

    k2b_kernel<<<1, 256>>>();

    k3_kernel<<<(Q4 + 255) / 256, 256>>>(out);
}

// round 17
// speedup vs baseline: 1.0983x; 1.0983x over previous
#include <cuda_runtime.h>

// ---------------- problem constants ----------------
#define O   130          // output spatial extent per axis
#define P   (O*O)        // 16900
#define O3  2197000      // 130^3
#define CH  12
// input x is 128^3

// ---------------- scratch (device globals) ----------------
// channel-quad layout: g_buf4[((q*O + z)*P + y*O + w)] = 4 permuted channels
__device__ float4 g_buf4[(size_t)3 * O3];
__device__ float  g_partial[10 * 67];
__device__ float  g_clip[2];

// shift offsets (oz, oy, ow) for the 6 one-hot dilated stencils, padded coords
__device__ constexpr int OFFS[6][3] = {
    {-1, 1, 1},   // s0: z-minus
    { 1, 1,-1},   // s1: w-minus
    { 1,-1, 1},   // s2: y-minus
    { 1, 1, 3},   // s3: w-plus
    { 3, 1, 1},   // s4: z-plus
    { 1, 3, 1}    // s5: y-plus
};
// quad partition of the 12 pairs: each quad spans exactly 4 shifts
__device__ constexpr int QS[3][4] = {        // shift ids per quad
    {0, 1, 2, 3},
    {0, 3, 4, 5},
    {1, 2, 4, 5}
};
__device__ constexpr int QP[3][4][2] = {     // channel pairs as local indices into QS[qd]
    { {1,0}, {2,0}, {2,1}, {3,2} },   // (1,0) (2,0) (2,1) (3,2)
    { {1,0}, {2,1}, {3,0}, {3,1} },   // (3,0) (4,3) (5,0) (5,3)
    { {2,0}, {2,1}, {3,0}, {3,2} }    // (4,1) (4,2) (5,1) (5,4)
};
// output channel id of each quad lane
__constant__ int CHMAP[12] = {0,1,2,4,  3,7,8,10,  5,6,9,11};

// ---------------- K1: 4 src planes -> two output z-planes per block ------------
#define STRIP 10
#define SR    14           // STRIP + 4 boxed halo rows
#define NSTRIP 13          // 13*10 = 130
#define RY    18           // padded-y source rows: jy in [y0-3, y0+14]
#define NPLANE 4           // source planes jz = z0-1, z0+1, z0+3, z0+5
#define SXN   (NPLANE*RY*134)   // 9648 floats
#define SRN   (SR*O)            // 1820 floats per row buffer
#define K1_SMEM ((SXN + 4*SRN) * 4)   // 67.7 KB
#define ZBLK 66            // 64 pair-blocks + 2 singletons

__global__ __launch_bounds__(256) void k1_kernel(const float* __restrict__ x) {
    extern __shared__ float sm[];
    float* s_x = sm;                       // [NPLANE][RY][134]
    float* s_r[4] = { sm + SXN, sm + SXN + SRN,
                      sm + SXN + 2*SRN, sm + SXN + 3*SRN };  // [SR][O] each

    const int by  = blockIdx.y;
    const int z0  = (by < 64) ? ((by >> 1) * 4 + (by & 1)) : (128 + (by - 64));
    const int nz  = (by < 64) ? 2 : 1;     // pair (z0, z0+2) or singleton
    const int y0  = blockIdx.x * STRIP;
    const int jy0 = y0 - 3;
    const int tid = threadIdx.x;

    // ---- fill NPLANE padded source planes (jz = z0-1 + 2p), one warp per row ----
    {
        const int wid  = tid >> 5;
        const int lane = tid & 31;
        for (int row = wid; row < NPLANE * RY; row += 8) {
            int p  = row / RY;
            int ry = row - p * RY;
            int jz = z0 + 2 * p - 1;
            int jy = jy0 + ry;
            bool rowok = (jz >= 0) & (jz <= 131) & (jy >= 0) & (jy <= 131);
            const float* xrow = x + ((size_t)min(max(jz - 2, 0), 127) << 14)
                                  + (min(max(jy - 2, 0), 127) << 7);
            float* srow = &s_x[(p * RY + ry) * 134];
            #pragma unroll
            for (int k = 0; k < 5; k++) {
                int i = lane + 32 * k;
                if (i < 134) {
                    bool ok = rowok & (i >= 1) & (i <= 132);
                    float v = 0.0f;
                    if (ok) v = __ldg(&xrow[min(max(i - 3, 0), 127)]);
                    srow[i] = v;
                }
            }
        }
    }
    __syncthreads();

    for (int zs = 0; zs < nz; zs++) {
        const int z = z0 + 2 * zs;     // output plane; its sources sit at slot +zs

        #pragma unroll
        for (int qd = 0; qd < 3; qd++) {
            // ---- W-box: 4 shift rows shared across 4 channels ----
            for (int idx = tid; idx < SR * NSTRIP; idx += 256) {
                int r  = idx / NSTRIP;
                int sg = idx - r * NSTRIP;
                int w0 = sg * 10;
                int ay = min(max(y0 - 2 + r, 0), O - 1);

                const float* R[4];
                #pragma unroll
                for (int l = 0; l < 4; l++) {
                    const int s  = QS[qd][l];
                    const int p  = ((OFFS[s][0] + 1) >> 1) + zs;
                    R[l] = &s_x[(p * RY + ay + OFFS[s][1] - jy0) * 134 + OFFS[s][2] + 1];
                }

                float d2[4][14];
                #pragma unroll
                for (int k = 0; k < 14; k++) {
                    int ww = min(max(w0 - 2 + k, 0), O - 1);
                    float v[4];
                    v[0] = R[0][ww]; v[1] = R[1][ww]; v[2] = R[2][ww]; v[3] = R[3][ww];
                    #pragma unroll
                    for (int j = 0; j < 4; j++) {
                        float d = v[QP[qd][j][0]] - v[QP[qd][j][1]];
                        d2[j][k] = d * d;
                    }
                }

                float s0 = d2[0][0] + d2[0][1] + d2[0][2] + d2[0][3] + d2[0][4];
                float s1 = d2[1][0] + d2[1][1] + d2[1][2] + d2[1][3] + d2[1][4];
                float s2 = d2[2][0] + d2[2][1] + d2[2][2] + d2[2][3] + d2[2][4];
                float s3 = d2[3][0] + d2[3][1] + d2[3][2] + d2[3][3] + d2[3][4];
                float* p0 = &s_r[0][r * O + w0];
                float* p1 = &s_r[1][r * O + w0];
                float* p2 = &s_r[2][r * O + w0];
                float* p3 = &s_r[3][r * O + w0];
                #pragma unroll
                for (int j = 0; j < 10; j++) {
                    p0[j] = s0; p1[j] = s1; p2[j] = s2; p3[j] = s3;
                    if (j < 9) {
                        s0 += d2[0][j + 5] - d2[0][j];
                        s1 += d2[1][j + 5] - d2[1][j];
                        s2 += d2[2][j + 5] - d2[2][j];
                        s3 += d2[3][j + 5] - d2[3][j];
                    }
                }
            }
            __syncthreads();

            // ---- H-box for 4 channels, write float4 ----
            float4* gb = &g_buf4[((size_t)qd * O + z) * P + (size_t)y0 * O];
            for (int idx = tid; idx < 2 * O; idx += 256) {
                int w   = idx % O;
                int ry0 = (idx / O) * 5;
                float t0[9], t1[9], t2[9], t3[9];
                #pragma unroll
                for (int k = 0; k < 9; k++) {
                    t0[k] = s_r[0][(ry0 + k) * O + w];
                    t1[k] = s_r[1][(ry0 + k) * O + w];
                    t2[k] = s_r[2][(ry0 + k) * O + w];
                    t3[k] = s_r[3][(ry0 + k) * O + w];
                }
                float s0 = t0[0] + t0[1] + t0[2] + t0[3] + t0[4];
                float s1 = t1[0] + t1[1] + t1[2] + t1[3] + t1[4];
                float s2 = t2[0] + t2[1] + t2[2] + t2[3] + t2[4];
                float s3 = t3[0] + t3[1] + t3[2] + t3[3] + t3[4];
                #pragma unroll
                for (int j = 0; j < 5; j++) {
                    gb[(ry0 + j) * O + w] = make_float4(s0, s1, s2, s3);
                    if (j < 4) {
                        s0 += t0[j + 5] - t0[j];
                        s1 += t1[j + 5] - t1[j];
                        s2 += t2[j + 5] - t2[j];
                        s3 += t3[j + 5] - t3[j];
                    }
                }
            }
            __syncthreads();
        }
    }
}

// ---------------- K2: z-box sweep, ring window (R13 rolled form) ---------------
#define ZCH  10
#define ZLEN 13
#define PBLK 67   // ceil(16900/256)

__global__ __launch_bounds__(256) void k2_kernel(float* __restrict__ mind) {
    const int tid = threadIdx.x;
    const int v   = blockIdx.x * 256 + tid;
    const int z0  = blockIdx.y * ZLEN;
    const int z1  = min(z0 + ZLEN, O);
    float acc = 0.0f;

    if (v < P) {
        float sums[CH], w0[CH], w1[CH], w2[CH], w3[CH];
        #pragma unroll
        for (int c = 0; c < CH; c++) sums[c] = 0.0f;

        #pragma unroll
        for (int q = 0; q < 4; q++) {
            int pz = min(max(z0 - 2 + q, 0), O - 1);
            float t[CH];
            #pragma unroll
            for (int qd = 0; qd < 3; qd++) {
                float4 u = g_buf4[((size_t)qd * O + pz) * P + v];
                t[4*qd] = u.x; t[4*qd+1] = u.y; t[4*qd+2] = u.z; t[4*qd+3] = u.w;
            }
            #pragma unroll
            for (int c = 0; c < CH; c++) {
                sums[c] += t[c];
                if (q == 0) w0[c] = t[c];
                else if (q == 1) w1[c] = t[c];
                else if (q == 2) w2[c] = t[c];
                else w3[c] = t[c];
            }
        }

        for (int z = z0; z < z1; z++) {
            int pz = min(z + 2, O - 1);
            float nv[CH];
            #pragma unroll
            for (int qd = 0; qd < 3; qd++) {
                float4 u = g_buf4[((size_t)qd * O + pz) * P + v];
                nv[4*qd] = u.x; nv[4*qd+1] = u.y; nv[4*qd+2] = u.z; nv[4*qd+3] = u.w;
            }
            #pragma unroll
            for (int c = 0; c < CH; c++) sums[c] += nv[c];

            float mn = sums[0], tot = sums[0];
            #pragma unroll
            for (int c = 1; c < CH; c++) { mn = fminf(mn, sums[c]); tot += sums[c]; }

            // write each permuted lane to its true output channel
            #pragma unroll
            for (int c = 0; c < CH; c++)
                mind[(size_t)CHMAP[c] * O3 + (size_t)z * P + v] =
                    (sums[c] - mn) * (1.0f / 125.0f);

            acc += (tot * (1.0f / 12.0f) - mn) * (1.0f / 125.0f);

            #pragma unroll
            for (int c = 0; c < CH; c++) {
                sums[c] -= w0[c];
                w0[c] = w1[c]; w1[c] = w2[c]; w2[c] = w3[c]; w3[c] = nv[c];
            }
        }
    }

    __shared__ float red[256];
    red[tid] = acc;
    __syncthreads();
    for (int s = 128; s > 0; s >>= 1) {
        if (tid < s) red[tid] += red[tid + s];
        __syncthreads();
    }
    if (tid == 0) g_partial[blockIdx.y * PBLK + blockIdx.x] = red[0];
}

// ---------------- K2b: deterministic final reduction -> clip bounds ------------
__global__ void k2b_kernel() {
    __shared__ float red[256];
    const int tid = threadIdx.x;
    float a = 0.0f;
    for (int i = tid; i < ZCH * PBLK; i += 256) a += g_partial[i];
    red[tid] = a;
    __syncthreads();
    for (int s = 128; s > 0; s >>= 1) {
        if (tid < s) red[tid] += red[tid + s];
        __syncthreads();
    }
    if (tid == 0) {
        float mean = red[0] / (float)O3;
        g_clip[0] = mean * 0.001f;
        g_clip[1] = mean * 1000.0f;
    }
}

// ---------------- K3: recompute var from channels, exp, float4 ----------------
#define Q4 (O3 / 4)    // 549250

__global__ __launch_bounds__(256) void k3_kernel(float* __restrict__ out) {
    const int v4 = blockIdx.x * 256 + threadIdx.x;
    if (v4 >= Q4) return;
    float4* o4 = (float4*)out;

    float4 m[CH];
    #pragma unroll
    for (int c = 0; c < CH; c++) m[c] = o4[(size_t)c * Q4 + v4];

    float sx = 0.f, sy = 0.f, sz = 0.f, sw = 0.f;
    #pragma unroll
    for (int c = 0; c < CH; c++) {
        sx += m[c].x; sy += m[c].y; sz += m[c].z; sw += m[c].w;
    }
    const float lo = g_clip[0], hi = g_clip[1];
    float ix = 1.0f / fminf(fmaxf(sx * (1.0f/12.0f), lo), hi);
    float iy = 1.0f / fminf(fmaxf(sy * (1.0f/12.0f), lo), hi);
    float iz = 1.0f / fminf(fmaxf(sz * (1.0f/12.0f), lo), hi);
    float iw = 1.0f / fminf(fmaxf(sw * (1.0f/12.0f), lo), hi);

    #pragma unroll
    for (int c = 0; c < CH; c++) {
        float4 r;
        r.x = __expf(-m[c].x * ix);
        r.y = __expf(-m[c].y * iy);
        r.z = __expf(-m[c].z * iz);
        r.w = __expf(-m[c].w * iw);
        o4[(size_t)c * Q4 + v4] = r;
    }
}

// ---------------- launch ----------------
extern "C" void kernel_launch(void* const* d_in, const int* in_sizes, int n_in,
                              void* d_out, int out_size) {
    const float* x = (const float*)d_in[0];
    float* out = (float*)d_out;

    cudaFuncSetAttribute(k1_kernel,
                         cudaFuncAttributeMaxDynamicSharedMemorySize, K1_SMEM);

    dim3 g1(NSTRIP, ZBLK);
    k1_kernel<<<g1, 256, K1_SMEM>>>(x);

    dim3 g2(PBLK, ZCH);
    k2_kernel<<<g2, 256>>>(out);

    k2b_kernel<<<1, 256>>>();

    k3_kernel<<<(Q4 + 255) / 256, 256>>>(out);
}